// round 2
// baseline (speedup 1.0000x reference)
#include <cuda_runtime.h>

// Problem constants (from reference_code)
#define Bn      64
#define h_img   416
#define w_img   416
#define H_out   608
#define W_out   608
#define ROW_OFF 85
#define COL_OFF 80

#define W4     (W_out / 4)    // 152 float4 per output row
#define w4_    (w_img / 4)    // 104 float4 per img row
#define X4_OFF (COL_OFF / 4)  // 20  (aligned: COL_OFF % 4 == 0)
#define YQ     (H_out / 4)    // 152 row-quads per image

__global__ void __launch_bounds__(256)
composite_kernel(const float4* __restrict__ img,   // [B,3,h,w] as float4
                 const float4* __restrict__ ref,   // [1,3,H,W] as float4
                 float4* __restrict__ out)         // [B,3,H,W] as float4
{
    const int total = Bn * YQ * W4;                // 1,478,656 threads
    int idx = blockIdx.x * blockDim.x + threadIdx.x;
    if (idx >= total) return;

    const int x4 = idx % W4;
    int t       = idx / W4;
    const int yq = t % YQ;
    const int b  = t / YQ;
    const int y0 = yq * 4;

    // ---- Front-batch: 12 ref loads (L2-resident, 4.4 MB tensor) ----
    float4 r[3][4];
    #pragma unroll
    for (int c = 0; c < 3; ++c) {
        const float4* rrow = ref + (size_t)(c * H_out + y0) * W4 + x4;
        #pragma unroll
        for (int j = 0; j < 4; ++j)
            r[c][j] = rrow[j * W4];
    }

    // ---- Composite region (only threads whose x-range overlaps) ----
    const int rx4 = x4 - X4_OFF;
    if (rx4 >= 0 && rx4 < w4_) {
        const size_t ibase = (size_t)b * 3 * h_img * w4_;
        #pragma unroll
        for (int j = 0; j < 4; ++j) {
            const int ry = y0 + j - ROW_OFF;
            if (ry >= 0 && ry < h_img) {
                // channel 2 is both the mask and the channel-2 payload
                const float4 m  = __ldcs(&img[ibase + (size_t)(2 * h_img + ry) * w4_ + rx4]);
                const float4 i0 = __ldcs(&img[ibase + (size_t)(0 * h_img + ry) * w4_ + rx4]);
                const float4 i1 = __ldcs(&img[ibase + (size_t)(1 * h_img + ry) * w4_ + rx4]);
                if (m.x != 0.0f) { r[0][j].x = i0.x; r[1][j].x = i1.x; r[2][j].x = m.x; }
                if (m.y != 0.0f) { r[0][j].y = i0.y; r[1][j].y = i1.y; r[2][j].y = m.y; }
                if (m.z != 0.0f) { r[0][j].z = i0.z; r[1][j].z = i1.z; r[2][j].z = m.z; }
                if (m.w != 0.0f) { r[0][j].w = i0.w; r[1][j].w = i1.w; r[2][j].w = m.w; }
            }
        }
    }

    // ---- 12 streaming stores (write-once, bypass L2 persistence) ----
    #pragma unroll
    for (int c = 0; c < 3; ++c) {
        float4* orow = out + (size_t)((b * 3 + c) * H_out + y0) * W4 + x4;
        #pragma unroll
        for (int j = 0; j < 4; ++j)
            __stcs(&orow[j * W4], r[c][j]);
    }
}

extern "C" void kernel_launch(void* const* d_in, const int* in_sizes, int n_in,
                              void* d_out, int out_size)
{
    const float4* img = (const float4*)d_in[0];   // [64,3,416,416] f32
    const float4* ref = (const float4*)d_in[1];   // [1,3,608,608]  f32
    float4* out = (float4*)d_out;                 // [64,3,608,608] f32

    const int total = Bn * YQ * W4;
    const int threads = 256;
    const int blocks = (total + threads - 1) / threads;
    composite_kernel<<<blocks, threads>>>(img, ref, out);
}

// round 3
// speedup vs baseline: 1.1444x; 1.1444x over previous
#include <cuda_runtime.h>

// Problem constants (from reference_code)
#define Bn      64
#define h_img   416
#define w_img   416
#define H_out   608
#define W_out   608
#define ROW_OFF 85
#define COL_OFF 80

#define W4     (W_out / 4)    // 152 float4 per output row
#define w4_    (w_img / 4)    // 104 float4 per img row
#define X4_OFF (COL_OFF / 4)  // 20  (aligned: COL_OFF % 4 == 0)

// W4 * H_out = 152 * 608 = 92416 = 361 * 256  -> exact grid, no bounds check

__global__ void __launch_bounds__(256, 8)
composite_kernel(const float4* __restrict__ img,   // [B,3,h,w] as float4
                 const float4* __restrict__ ref,   // [1,3,H,W] as float4
                 float4* __restrict__ out)         // [B,3,H,W] as float4
{
    const int idx = blockIdx.x * 256 + threadIdx.x;   // 0 .. 92415, covers (y, x4)
    const int b   = blockIdx.y;

    const int x4 = idx % W4;
    const int y  = idx / W4;

    // Reference pixels, all 3 channels (4.4 MB tensor -> L2-resident)
    const float4 r0 = ref[(size_t)(0 * H_out + y) * W4 + x4];
    const float4 r1 = ref[(size_t)(1 * H_out + y) * W4 + x4];
    const float4 r2 = ref[(size_t)(2 * H_out + y) * W4 + x4];

    float4 o0 = r0, o1 = r1, o2 = r2;

    const int ry  = y  - ROW_OFF;
    const int rx4 = x4 - X4_OFF;
    if (ry >= 0 && ry < h_img && rx4 >= 0 && rx4 < w4_) {
        const size_t ibase = (size_t)b * 3 * h_img * w4_ + (size_t)ry * w4_ + rx4;
        // channel 2 is both mask and payload; stream (read-once) to keep L2 for ref
        const float4 m  = __ldcs(&img[ibase + (size_t)2 * h_img * w4_]);
        const float4 i0 = __ldcs(&img[ibase]);
        const float4 i1 = __ldcs(&img[ibase + (size_t)1 * h_img * w4_]);

        if (m.x != 0.0f) { o0.x = i0.x; o1.x = i1.x; o2.x = m.x; }
        if (m.y != 0.0f) { o0.y = i0.y; o1.y = i1.y; o2.y = m.y; }
        if (m.z != 0.0f) { o0.z = i0.z; o1.z = i1.z; o2.z = m.z; }
        if (m.w != 0.0f) { o0.w = i0.w; o1.w = i1.w; o2.w = m.w; }
    }

    const size_t obase = (size_t)b * 3 * H_out * W4 + (size_t)y * W4 + x4;
    __stcs(&out[obase],                            o0);
    __stcs(&out[obase + (size_t)1 * H_out * W4],   o1);
    __stcs(&out[obase + (size_t)2 * H_out * W4],   o2);
}

extern "C" void kernel_launch(void* const* d_in, const int* in_sizes, int n_in,
                              void* d_out, int out_size)
{
    const float4* img = (const float4*)d_in[0];   // [64,3,416,416] f32
    const float4* ref = (const float4*)d_in[1];   // [1,3,608,608]  f32
    float4* out = (float4*)d_out;                 // [64,3,608,608] f32

    dim3 grid(361, Bn);   // 361*256 == 152*608 exactly; y-dim = batch
    composite_kernel<<<grid, 256>>>(img, ref, out);
}